// round 2
// baseline (speedup 1.0000x reference)
#include <cuda_runtime.h>
#include <cuda_fp16.h>

// Problem constants (fixed by reference setup)
#define LQ      4096
#define NBATCH  8
#define CDIM    256
#define NHEADS  8
#define NLVL    4
#define NPTS    4
#define MROWS   (NBATCH * LQ)            // 32768
#define LTOT    13294
#define FM_ELEMS (LTOT * NBATCH * CDIM)  // 27,226,112

// Scratch (device globals; allocation in kernel_launch is forbidden)
__device__ float  g_off[(size_t)MROWS * 256];      // sampling offsets (N*Lq, H*L*P*2)
__device__ float  g_attnlog[(size_t)MROWS * 128];  // attention logits (N*Lq, H*L*P)
__device__ float  g_val[(size_t)MROWS * 256];      // sampled+weighted values (N*Lq, C)
__device__ __half g_fmh[(size_t)FM_ELEMS];         // fp16 feature maps

// ---------------------------------------------------------------------------
// Feature map fp32 -> fp16 conversion (halves L2 gather traffic in sampling)
// ---------------------------------------------------------------------------
__global__ void fm2half_kernel(const float4* __restrict__ fm4) {
    const int n4 = FM_ELEMS / 4;
    int i = blockIdx.x * blockDim.x + threadIdx.x;
    const int stride = gridDim.x * blockDim.x;
    for (; i < n4; i += stride) {
        float4 v = fm4[i];
        __half2* o = reinterpret_cast<__half2*>(g_fmh) + (size_t)i * 2;
        o[0] = __floats2half2_rn(v.x, v.y);
        o[1] = __floats2half2_rn(v.z, v.w);
    }
}

// ---------------------------------------------------------------------------
// SGEMM: C[M x Ncols] = A[M x 256] * B[256 x Ncols] + bias
//   BM=128, BN=128, BK=8, 256 threads, 8x8 register tile per thread.
//   A_Q    : A is the query tensor in (Lq, N, C) layout, logical row m=n*Lq+lq
//   OUT_T  : write output transposed into (Lq, N, C) layout (final projection)
//   M = 32768 (multiple of 128), K = 256, Ncols in {128, 256} -> no bounds checks
// ---------------------------------------------------------------------------
template <int A_Q, int OUT_T>
__global__ __launch_bounds__(256) void sgemm128(
    const float* __restrict__ A, const float* __restrict__ B,
    const float* __restrict__ bias, float* __restrict__ Cmat, int Ncols)
{
    const int K = 256;
    __shared__ float As[8][128];
    __shared__ float Bs[8][128];

    const int tid = threadIdx.x;
    const int bm  = blockIdx.y * 128;
    const int bn  = blockIdx.x * 128;
    const int nB  = bm >> 12;      // bm / 4096 (rows of one block never cross n)
    const int lq0 = bm & 4095;

    const float* Aptr;
    size_t aStride;
    if (A_Q) { Aptr = A + (size_t)lq0 * (NBATCH * CDIM) + (size_t)nB * CDIM; aStride = NBATCH * CDIM; }
    else     { Aptr = A + (size_t)bm * K;                                    aStride = K; }

    const int aRow = tid >> 1;          // 0..127
    const int aK   = (tid & 1) * 4;     // 0 or 4
    const int bK   = tid >> 5;          // 0..7
    const int bCol = (tid & 31) << 2;   // 0..124
    const int ty   = tid >> 4;          // 0..15
    const int tx   = tid & 15;          // 0..15

    float acc[8][8];
#pragma unroll
    for (int i = 0; i < 8; i++)
#pragma unroll
        for (int j = 0; j < 8; j++) acc[i][j] = 0.f;

    for (int kt = 0; kt < K; kt += 8) {
        float4 a4 = *reinterpret_cast<const float4*>(Aptr + (size_t)aRow * aStride + kt + aK);
        float4 b4 = *reinterpret_cast<const float4*>(B + (size_t)(kt + bK) * Ncols + bn + bCol);
        __syncthreads();
        As[aK + 0][aRow] = a4.x;
        As[aK + 1][aRow] = a4.y;
        As[aK + 2][aRow] = a4.z;
        As[aK + 3][aRow] = a4.w;
        *reinterpret_cast<float4*>(&Bs[bK][bCol]) = b4;
        __syncthreads();
#pragma unroll
        for (int k = 0; k < 8; k++) {
            float a[8], b[8];
            *reinterpret_cast<float4*>(a)     = *reinterpret_cast<const float4*>(&As[k][ty * 8]);
            *reinterpret_cast<float4*>(a + 4) = *reinterpret_cast<const float4*>(&As[k][ty * 8 + 4]);
            *reinterpret_cast<float4*>(b)     = *reinterpret_cast<const float4*>(&Bs[k][tx * 8]);
            *reinterpret_cast<float4*>(b + 4) = *reinterpret_cast<const float4*>(&Bs[k][tx * 8 + 4]);
#pragma unroll
            for (int i = 0; i < 8; i++)
#pragma unroll
                for (int j = 0; j < 8; j++) acc[i][j] = fmaf(a[i], b[j], acc[i][j]);
        }
    }

#pragma unroll
    for (int i = 0; i < 8; i++) {
        float* outRow;
        if (OUT_T)
            outRow = Cmat + (size_t)(lq0 + ty * 8 + i) * (NBATCH * CDIM) + (size_t)nB * CDIM;
        else
            outRow = Cmat + (size_t)(bm + ty * 8 + i) * Ncols;
#pragma unroll
        for (int j = 0; j < 8; j += 4) {
            const int col = bn + tx * 8 + j;
            float4 v;
            v.x = acc[i][j + 0] + bias[col + 0];
            v.y = acc[i][j + 1] + bias[col + 1];
            v.z = acc[i][j + 2] + bias[col + 2];
            v.w = acc[i][j + 3] + bias[col + 3];
            *reinterpret_cast<float4*>(outRow + col) = v;
        }
    }
}

// ---------------------------------------------------------------------------
// Sampling: one warp per (n, lq, head); lane = channel within head (dh=32).
// Fuses the 16-wide softmax (shuffle-based) and the attn-weighted bilinear
// accumulation over 4 levels x 4 points. Gathers are 64B-contiguous fp16.
// ---------------------------------------------------------------------------
__global__ __launch_bounds__(256) void sample_kernel(const float* __restrict__ rp) {
    const int gid  = blockIdx.x * blockDim.x + threadIdx.x;
    const int lane = gid & 31;
    const int warp = gid >> 5;
    const int h    = warp & 7;
    const int mq   = warp >> 3;          // 0..32767  (= n*Lq + lq)
    const int n    = mq >> 12;
    // const int lq = mq & 4095;         // implicit in mq

    // ---- softmax over the 16 (level, point) logits of this head ----
    float logit = -3.0e38f;
    if (lane < 16) logit = g_attnlog[(size_t)mq * 128 + h * 16 + lane];
    float mx = logit;
#pragma unroll
    for (int o = 16; o > 0; o >>= 1) mx = fmaxf(mx, __shfl_xor_sync(0xffffffffu, mx, o));
    float e = (lane < 16) ? expf(logit - mx) : 0.f;
    float ssum = e;
#pragma unroll
    for (int o = 16; o > 0; o >>= 1) ssum += __shfl_xor_sync(0xffffffffu, ssum, o);
    const float w = e / ssum;

    // ---- sampling offsets: lane i (<16) holds (dx, dy) of point i ----
    float2 off2 = make_float2(0.f, 0.f);
    if (lane < 16)
        off2 = reinterpret_cast<const float2*>(g_off + (size_t)mq * 256)[h * 16 + lane];

    const __half* fbase = g_fmh + n * CDIM + h * 32 + lane;   // + pos * (N*C)
    const float*  rpb   = rp + (size_t)mq * (NLVL * 2);

    float acc = 0.f;
#pragma unroll
    for (int l = 0; l < NLVL; l++) {
        const int kW[4] = {100, 50, 25, 13};
        const int kS[4] = {0, 10000, 12500, 13125};
        const int Wl = kW[l], Hl = kW[l], S = kS[l];
        const float invW = 1.f / (float)Wl, invH = 1.f / (float)Hl;
        const float rpx = __ldg(rpb + l * 2 + 0);
        const float rpy = __ldg(rpb + l * 2 + 1);
#pragma unroll
        for (int p = 0; p < NPTS; p++) {
            const int src = l * 4 + p;
            const float wt = __shfl_sync(0xffffffffu, w, src);
            const float ox = __shfl_sync(0xffffffffu, off2.x, src);
            const float oy = __shfl_sync(0xffffffffu, off2.y, src);
            // grid_sample coords (align_corners=False): x = loc_x*W - 0.5
            const float x = fmaf(rpx + ox * invW, (float)Wl, -0.5f);
            const float y = fmaf(rpy + oy * invH, (float)Hl, -0.5f);
            const float x0f = floorf(x), y0f = floorf(y);
            const float wx = x - x0f, wy = y - y0f;
            const int x0 = (int)x0f, y0 = (int)y0f;
            const int x1 = x0 + 1, y1 = y0 + 1;
            const bool vx0 = (x0 >= 0) && (x0 < Wl), vx1 = (x1 >= 0) && (x1 < Wl);
            const bool vy0 = (y0 >= 0) && (y0 < Hl), vy1 = (y1 >= 0) && (y1 < Hl);
            const int cx0 = min(max(x0, 0), Wl - 1), cx1 = min(max(x1, 0), Wl - 1);
            const int cy0 = min(max(y0, 0), Hl - 1), cy1 = min(max(y1, 0), Hl - 1);
            float v00 = 0.f, v01 = 0.f, v10 = 0.f, v11 = 0.f;
            if (vy0) {
                const int rbase = S + cy0 * Wl;
                if (vx0) v00 = __half2float(__ldg(fbase + (size_t)(rbase + cx0) * (NBATCH * CDIM)));
                if (vx1) v01 = __half2float(__ldg(fbase + (size_t)(rbase + cx1) * (NBATCH * CDIM)));
            }
            if (vy1) {
                const int rbase = S + cy1 * Wl;
                if (vx0) v10 = __half2float(__ldg(fbase + (size_t)(rbase + cx0) * (NBATCH * CDIM)));
                if (vx1) v11 = __half2float(__ldg(fbase + (size_t)(rbase + cx1) * (NBATCH * CDIM)));
            }
            const float iwx = 1.f - wx, iwy = 1.f - wy;
            acc += wt * (iwy * (iwx * v00 + wx * v01) + wy * (iwx * v10 + wx * v11));
        }
    }
    g_val[(size_t)mq * 256 + h * 32 + lane] = acc;
}

// ---------------------------------------------------------------------------
// kernel_launch: conversion -> off/attn GEMMs -> sampling -> output GEMM
// ---------------------------------------------------------------------------
extern "C" void kernel_launch(void* const* d_in, const int* in_sizes, int n_in,
                              void* d_out, int out_size) {
    const float* query  = (const float*)d_in[0];  // (Lq, N, C)
    const float* rp     = (const float*)d_in[1];  // (N, Lq, 4, 2)
    const float* fm     = (const float*)d_in[2];  // (L_total, N, C)
    // d_in[3]: spatial_shapes (compile-time constant here)
    const float* W_off  = (const float*)d_in[4];
    const float* b_off  = (const float*)d_in[5];
    const float* W_attn = (const float*)d_in[6];
    const float* b_attn = (const float*)d_in[7];
    const float* W_out  = (const float*)d_in[8];
    const float* b_out  = (const float*)d_in[9];
    float* out = (float*)d_out;

    float *p_off, *p_attn, *p_val;
    cudaGetSymbolAddress((void**)&p_off,  g_off);
    cudaGetSymbolAddress((void**)&p_attn, g_attnlog);
    cudaGetSymbolAddress((void**)&p_val,  g_val);

    // 1) feature maps -> fp16
    fm2half_kernel<<<1024, 256>>>(reinterpret_cast<const float4*>(fm));

    // 2) offset + attention-logit projections (fp32 GEMMs)
    sgemm128<1, 0><<<dim3(2, 256), 256>>>(query, W_off,  b_off,  p_off,  256);
    sgemm128<1, 0><<<dim3(1, 256), 256>>>(query, W_attn, b_attn, p_attn, 128);

    // 3) fused softmax + bilinear sampling + attention-weighted accumulation
    sample_kernel<<<MROWS * NHEADS / 8, 256>>>(rp);

    // 4) output projection, epilogue writes (Lq, N, C) directly
    sgemm128<0, 1><<<dim3(2, 256), 256>>>(p_val, W_out, b_out, out, 256);
}

// round 6
// speedup vs baseline: 1.9874x; 1.9874x over previous
#include <cuda_runtime.h>
#include <cuda_fp16.h>
#include <cstdint>

// Problem constants (fixed by reference setup)
#define LQ      4096
#define NBATCH  8
#define CDIM    256
#define NHEADS  8
#define NLVL    4
#define NPTS    4
#define MROWS   (NBATCH * LQ)            // 32768
#define LTOT    13294
#define FM_ELEMS (LTOT * NBATCH * CDIM)  // 27,226,112

// Scratch (device globals; allocation in kernel_launch is forbidden)
__device__ float  g_off[(size_t)MROWS * 256];      // sampling offsets (N*Lq, H*L*P*2)
__device__ float  g_attnlog[(size_t)MROWS * 128];  // attention logits (N*Lq, H*L*P)
__device__ float  g_val[(size_t)MROWS * 256];      // sampled+weighted values (N*Lq, C)
__device__ __half g_fmh[(size_t)FM_ELEMS];         // fp16 feature maps

// ---------------------------------------------------------------------------
// Feature map fp32 -> fp16 conversion
// ---------------------------------------------------------------------------
__global__ void fm2half_kernel(const float4* __restrict__ fm4) {
    const int n4 = FM_ELEMS / 4;
    int i = blockIdx.x * blockDim.x + threadIdx.x;
    const int stride = gridDim.x * blockDim.x;
    for (; i < n4; i += stride) {
        float4 v = fm4[i];
        __half2* o = reinterpret_cast<__half2*>(g_fmh) + (size_t)i * 2;
        o[0] = __floats2half2_rn(v.x, v.y);
        o[1] = __floats2half2_rn(v.z, v.w);
    }
}

// ---------------------------------------------------------------------------
// TF32 tensor-core GEMM: C[M x Ncols] = A[M x 256] * B[256 x Ncols] + bias
//   BM=128, BN=128, BK=16, 256 threads = 8 warps (2 x 4), warp tile 64x32,
//   mma.sync.aligned.m16n8k8.row.col.f32.tf32.tf32.f32
//   tf32 values are carried as uint32_t bit patterns (cvt.rna.tf32 needs .b32 dst).
// ---------------------------------------------------------------------------
__device__ __forceinline__ uint32_t to_tf32(float x) {
    uint32_t r; asm("cvt.rna.tf32.f32 %0, %1;" : "=r"(r) : "f"(x)); return r;
}

__device__ __forceinline__ void mma_tf32(float* d, const uint32_t* a, const uint32_t* b) {
    asm volatile(
        "mma.sync.aligned.m16n8k8.row.col.f32.tf32.tf32.f32 "
        "{%0,%1,%2,%3}, {%4,%5,%6,%7}, {%8,%9}, {%0,%1,%2,%3};\n"
        : "+f"(d[0]), "+f"(d[1]), "+f"(d[2]), "+f"(d[3])
        : "r"(a[0]), "r"(a[1]), "r"(a[2]), "r"(a[3]), "r"(b[0]), "r"(b[1]));
}

#define AS_LD 20    // As row stride (words): conflict-free for frag loads
#define BS_LD 136   // Bs row stride (words): conflict-free for frag loads

template <int A_Q, int OUT_T>
__global__ __launch_bounds__(256) void mma_gemm(
    const float* __restrict__ A, const float* __restrict__ B,
    const float* __restrict__ bias, float* __restrict__ Cmat, int Ncols)
{
    __shared__ uint32_t As[128 * AS_LD];   // [m][k] padded, tf32 bit patterns
    __shared__ uint32_t Bs[16 * BS_LD];    // [k][n] padded, tf32 bit patterns

    const int tid  = threadIdx.x;
    const int lane = tid & 31;
    const int warp = tid >> 5;
    const int wm   = (warp & 1) * 64;   // warp M offset
    const int wn   = (warp >> 1) * 32;  // warp N offset
    const int grp  = lane >> 2;         // 0..7
    const int tg   = lane & 3;          // 0..3

    const int bm  = blockIdx.y * 128;
    const int bn  = blockIdx.x * 128;
    const int nB  = bm >> 12;           // block never crosses batch boundary
    const int lq0 = bm & 4095;

    const float* Aptr;
    int aStride;
    if (A_Q) { Aptr = A + (size_t)lq0 * (NBATCH * CDIM) + (size_t)nB * CDIM; aStride = NBATCH * CDIM; }
    else     { Aptr = A + (size_t)bm * CDIM;                                 aStride = CDIM; }

    // global-load mapping: 512 float4 per tile for each of A,B; 2 per thread
    const int aRow0 = tid >> 2;           // 0..63   (+64 for second)
    const int aKq   = (tid & 3) * 4;
    const int bRow0 = tid >> 5;           // 0..7    (+8 for second)
    const int bCq   = (tid & 31) * 4;

    float acc[4][4][4];
#pragma unroll
    for (int i = 0; i < 4; i++)
#pragma unroll
        for (int j = 0; j < 4; j++)
#pragma unroll
            for (int k = 0; k < 4; k++) acc[i][j][k] = 0.f;

    for (int kt = 0; kt < CDIM; kt += 16) {
        float4 a0 = *reinterpret_cast<const float4*>(Aptr + (size_t)aRow0 * aStride + kt + aKq);
        float4 a1 = *reinterpret_cast<const float4*>(Aptr + (size_t)(aRow0 + 64) * aStride + kt + aKq);
        float4 b0 = *reinterpret_cast<const float4*>(B + (size_t)(kt + bRow0) * Ncols + bn + bCq);
        float4 b1 = *reinterpret_cast<const float4*>(B + (size_t)(kt + bRow0 + 8) * Ncols + bn + bCq);
        __syncthreads();
        {
            uint4 c;
            c.x = to_tf32(a0.x); c.y = to_tf32(a0.y); c.z = to_tf32(a0.z); c.w = to_tf32(a0.w);
            *reinterpret_cast<uint4*>(&As[aRow0 * AS_LD + aKq]) = c;
            c.x = to_tf32(a1.x); c.y = to_tf32(a1.y); c.z = to_tf32(a1.z); c.w = to_tf32(a1.w);
            *reinterpret_cast<uint4*>(&As[(aRow0 + 64) * AS_LD + aKq]) = c;
            c.x = to_tf32(b0.x); c.y = to_tf32(b0.y); c.z = to_tf32(b0.z); c.w = to_tf32(b0.w);
            *reinterpret_cast<uint4*>(&Bs[bRow0 * BS_LD + bCq]) = c;
            c.x = to_tf32(b1.x); c.y = to_tf32(b1.y); c.z = to_tf32(b1.z); c.w = to_tf32(b1.w);
            *reinterpret_cast<uint4*>(&Bs[(bRow0 + 8) * BS_LD + bCq]) = c;
        }
        __syncthreads();

#pragma unroll
        for (int kk = 0; kk < 16; kk += 8) {
            uint32_t af[4][4], bf[4][2];
#pragma unroll
            for (int mi = 0; mi < 4; mi++) {
                const int mr = wm + mi * 16 + grp;
                af[mi][0] = As[mr * AS_LD + kk + tg];
                af[mi][1] = As[(mr + 8) * AS_LD + kk + tg];
                af[mi][2] = As[mr * AS_LD + kk + 4 + tg];
                af[mi][3] = As[(mr + 8) * AS_LD + kk + 4 + tg];
            }
#pragma unroll
            for (int ni = 0; ni < 4; ni++) {
                const int nc = wn + ni * 8 + grp;
                bf[ni][0] = Bs[(kk + tg) * BS_LD + nc];
                bf[ni][1] = Bs[(kk + 4 + tg) * BS_LD + nc];
            }
#pragma unroll
            for (int mi = 0; mi < 4; mi++)
#pragma unroll
                for (int ni = 0; ni < 4; ni++)
                    mma_tf32(acc[mi][ni], af[mi], bf[ni]);
        }
    }

    // Epilogue: c0:(r,c) c1:(r,c+1) c2:(r+8,c) c3:(r+8,c+1); r=grp, c=2*tg
#pragma unroll
    for (int mi = 0; mi < 4; mi++) {
#pragma unroll
        for (int ni = 0; ni < 4; ni++) {
            const int row = wm + mi * 16 + grp;
            const int col = bn + wn + ni * 8 + tg * 2;
            const float bx = bias[col], by = bias[col + 1];
            float* r0;
            float* r1;
            if (OUT_T) {
                r0 = Cmat + (size_t)(lq0 + row) * (NBATCH * CDIM) + (size_t)nB * CDIM + col;
                r1 = Cmat + (size_t)(lq0 + row + 8) * (NBATCH * CDIM) + (size_t)nB * CDIM + col;
            } else {
                r0 = Cmat + (size_t)(bm + row) * Ncols + col;
                r1 = Cmat + (size_t)(bm + row + 8) * Ncols + col;
            }
            float2 v0 = make_float2(acc[mi][ni][0] + bx, acc[mi][ni][1] + by);
            float2 v1 = make_float2(acc[mi][ni][2] + bx, acc[mi][ni][3] + by);
            *reinterpret_cast<float2*>(r0) = v0;
            *reinterpret_cast<float2*>(r1) = v1;
        }
    }
}

// ---------------------------------------------------------------------------
// Sampling: one warp per (mq, head-pair). Lanes 0-15 serve head 2hp,
// lanes 16-31 serve head 2hp+1; each lane handles 2 channels via __half2.
// Halves warp count (and thus scalar coord/clamp/shuffle work) vs 1-head/warp.
// ---------------------------------------------------------------------------
__global__ __launch_bounds__(256) void sample_kernel(const float* __restrict__ rp) {
    const int gid  = blockIdx.x * blockDim.x + threadIdx.x;
    const int lane = gid & 31;
    const int warp = gid >> 5;
    const int hp   = warp & 3;           // head pair 0..3
    const int mq   = warp >> 2;          // 0..32767 (= n*Lq + lq)
    const int n    = mq >> 12;

    // ---- softmax over this head's 16 logits (within each 16-lane half) ----
    const float logit = g_attnlog[(size_t)mq * 128 + hp * 32 + lane];
    float mx = logit;
#pragma unroll
    for (int o = 8; o > 0; o >>= 1) mx = fmaxf(mx, __shfl_xor_sync(0xffffffffu, mx, o));
    const float e = __expf(logit - mx);
    float ssum = e;
#pragma unroll
    for (int o = 8; o > 0; o >>= 1) ssum += __shfl_xor_sync(0xffffffffu, ssum, o);
    const float w = e / ssum;

    // ---- sampling offset of this lane's point: (dx, dy) ----
    const float2 off2 = reinterpret_cast<const float2*>(g_off + (size_t)mq * 256)[hp * 32 + lane];

    // base pointer in half2 units: element (pos, n, h*32 + c2*2)
    const __half2* fbase = reinterpret_cast<const __half2*>(g_fmh) + n * 128 + hp * 32 + lane;
    const float* rpb = rp + (size_t)mq * (NLVL * 2);

    const int broadBase = lane & 16;     // shuffle source stays in own half
    float2 acc = make_float2(0.f, 0.f);

#pragma unroll
    for (int l = 0; l < NLVL; l++) {
        const int kW[4] = {100, 50, 25, 13};
        const int kS[4] = {0, 10000, 12500, 13125};
        const int Wl = kW[l], Hl = kW[l], S = kS[l];
        // x = rp.x * W - 0.5 + ox   (off/W then *W cancels exactly)
        const float bx = fmaf(__ldg(rpb + l * 2 + 0), (float)Wl, -0.5f);
        const float by = fmaf(__ldg(rpb + l * 2 + 1), (float)Hl, -0.5f);
#pragma unroll
        for (int p = 0; p < NPTS; p++) {
            const int src = broadBase | (l * 4 + p);
            const float wt = __shfl_sync(0xffffffffu, w, src);
            const float ox = __shfl_sync(0xffffffffu, off2.x, src);
            const float oy = __shfl_sync(0xffffffffu, off2.y, src);
            const float x = bx + ox;
            const float y = by + oy;
            const float x0f = floorf(x), y0f = floorf(y);
            const float wx = x - x0f, wy = y - y0f;
            const int x0 = (int)x0f, y0 = (int)y0f;
            const int x1 = x0 + 1, y1 = y0 + 1;
            const bool vx0 = (unsigned)x0 < (unsigned)Wl;
            const bool vx1 = (unsigned)x1 < (unsigned)Wl;
            const bool vy0 = (unsigned)y0 < (unsigned)Hl;
            const bool vy1 = (unsigned)y1 < (unsigned)Hl;
            const __half2 hz = __float2half2_rn(0.f);
            __half2 h00 = hz, h01 = hz, h10 = hz, h11 = hz;
            if (vy0) {
                const unsigned rb = (unsigned)(S + y0 * Wl);
                if (vx0) h00 = __ldg(fbase + (size_t)((rb + x0) << 10));
                if (vx1) h01 = __ldg(fbase + (size_t)((rb + x1) << 10));
            }
            if (vy1) {
                const unsigned rb = (unsigned)(S + y1 * Wl);
                if (vx0) h10 = __ldg(fbase + (size_t)((rb + x0) << 10));
                if (vx1) h11 = __ldg(fbase + (size_t)((rb + x1) << 10));
            }
            const float2 f00 = __half22float2(h00);
            const float2 f01 = __half22float2(h01);
            const float2 f10 = __half22float2(h10);
            const float2 f11 = __half22float2(h11);
            const float iwx = 1.f - wx, iwy = 1.f - wy;
            const float w00 = iwx * iwy, w01 = wx * iwy, w10 = iwx * wy, w11 = wx * wy;
            acc.x += wt * (w00 * f00.x + w01 * f01.x + w10 * f10.x + w11 * f11.x);
            acc.y += wt * (w00 * f00.y + w01 * f01.y + w10 * f10.y + w11 * f11.y);
        }
    }
    reinterpret_cast<float2*>(g_val + (size_t)mq * 256)[hp * 32 + lane] = acc;
}

// ---------------------------------------------------------------------------
// kernel_launch
// ---------------------------------------------------------------------------
extern "C" void kernel_launch(void* const* d_in, const int* in_sizes, int n_in,
                              void* d_out, int out_size) {
    const float* query  = (const float*)d_in[0];  // (Lq, N, C)
    const float* rp     = (const float*)d_in[1];  // (N, Lq, 4, 2)
    const float* fm     = (const float*)d_in[2];  // (L_total, N, C)
    const float* W_off  = (const float*)d_in[4];
    const float* b_off  = (const float*)d_in[5];
    const float* W_attn = (const float*)d_in[6];
    const float* b_attn = (const float*)d_in[7];
    const float* W_out  = (const float*)d_in[8];
    const float* b_out  = (const float*)d_in[9];
    float* out = (float*)d_out;

    float *p_off, *p_attn, *p_val;
    cudaGetSymbolAddress((void**)&p_off,  g_off);
    cudaGetSymbolAddress((void**)&p_attn, g_attnlog);
    cudaGetSymbolAddress((void**)&p_val,  g_val);

    // 1) feature maps -> fp16
    fm2half_kernel<<<2048, 256>>>(reinterpret_cast<const float4*>(fm));

    // 2) offset + attention-logit projections (tf32 tensor-core GEMMs)
    mma_gemm<1, 0><<<dim3(2, 256), 256>>>(query, W_off,  b_off,  p_off,  256);
    mma_gemm<1, 0><<<dim3(1, 256), 256>>>(query, W_attn, b_attn, p_attn, 128);

    // 3) fused softmax + bilinear sampling + attention-weighted accumulation
    sample_kernel<<<MROWS * 4 / 8, 256>>>(rp);

    // 4) output projection, epilogue writes (Lq, N, C) directly
    mma_gemm<0, 1><<<dim3(2, 256), 256>>>(p_val, W_out, b_out, out, 256);
}